// round 8
// baseline (speedup 1.0000x reference)
#include <cuda_runtime.h>
#include <cuda_fp16.h>
#include <cstdint>

// ============================================================================
// LowRankBilinearFusion, HMMA fp16:
//   prep: u,v -> fp16 hi/lo; Wu,Wv,Wp -> fp16
//   proj: up_part = u@Wu^T (k-split x2), vp_part = v@Wv^T (k-split x4), K=512/CTA
//   add:  up = sum2 (fp32), vp16 = fp16(sum4)
//   fuse: out[bm] = relu((vp16[b] ⊙ up16[bm]) @ Wp16^T + bp)
//         grid 128 CTAs x 8 bm; Wp + A smem-resident; 64x64 warp tiles;
//         barrier-free MMA loop.
// ============================================================================

__device__ float  g_up[1024 * 256];
__device__ float  g_up_part[2 * 1024 * 256];
__device__ float  g_vp_part[4 * 4096 * 256];
__device__ __half g_vp16[4096 * 256];
__device__ __half g_uh[1024 * 1024], g_ul[1024 * 1024];
__device__ __half g_vh[4096 * 2048], g_vl[4096 * 2048];
__device__ __half g_wu16[256 * 1024];
__device__ __half g_wv16[256 * 2048];
__device__ __half g_wp16[256 * 256];

#define SWZ(o) ((o) ^ (((o) >> 3) & 0x70))

__device__ __forceinline__ uint32_t smem_u32(const void* p) {
    uint32_t a;
    asm("{ .reg .u64 t; cvta.to.shared.u64 t, %1; cvt.u32.u64 %0, t; }" : "=r"(a) : "l"(p));
    return a;
}
__device__ __forceinline__ void ldsm4(uint32_t& r0, uint32_t& r1, uint32_t& r2, uint32_t& r3,
                                      uint32_t addr) {
    asm volatile("ldmatrix.sync.aligned.m8n8.x4.shared.b16 {%0,%1,%2,%3}, [%4];"
                 : "=r"(r0), "=r"(r1), "=r"(r2), "=r"(r3) : "r"(addr));
}
__device__ __forceinline__ void mma_f16(float* c, const uint32_t* a, const uint32_t* b) {
    asm volatile(
        "mma.sync.aligned.m16n8k16.row.col.f32.f16.f16.f32 "
        "{%0,%1,%2,%3}, {%4,%5,%6,%7}, {%8,%9}, {%0,%1,%2,%3};"
        : "+f"(c[0]), "+f"(c[1]), "+f"(c[2]), "+f"(c[3])
        : "r"(a[0]), "r"(a[1]), "r"(a[2]), "r"(a[3]), "r"(b[0]), "r"(b[1]));
}
__device__ __forceinline__ void cp16(uint32_t dst, const void* src) {
    asm volatile("cp.async.cg.shared.global [%0], [%1], 16;" :: "r"(dst), "l"(src));
}
__device__ __forceinline__ void cp_commit() { asm volatile("cp.async.commit_group;" ::: "memory"); }
template <int N>
__device__ __forceinline__ void cp_wait() { asm volatile("cp.async.wait_group %0;" :: "n"(N) : "memory"); }

// -------------------- prep: split inputs, convert weights --------------------
__global__ void __launch_bounds__(256) prep_cvt(
    const float* __restrict__ u, const float* __restrict__ v,
    const float* __restrict__ Wu, const float* __restrict__ Wv, const float* __restrict__ Wp,
    __half* uh, __half* ul, __half* vh, __half* vl,
    __half* wu, __half* wv, __half* wp)
{
    const int N1 = 1024 * 1024, N2 = 4096 * 2048;
    const int N3 = 256 * 1024, N4 = 256 * 2048, N5 = 256 * 256;
    int i = blockIdx.x * 256 + threadIdx.x;
    if (i < N1) {
        float x = u[i];
        __half h = __float2half_rn(x);
        uh[i] = h; ul[i] = __float2half_rn(x - __half2float(h));
    } else if (i < N1 + N2) {
        int j = i - N1;
        float x = v[j];
        __half h = __float2half_rn(x);
        vh[j] = h; vl[j] = __float2half_rn(x - __half2float(h));
    } else if (i < N1 + N2 + N3) {
        int j = i - N1 - N2; wu[j] = __float2half_rn(Wu[j]);
    } else if (i < N1 + N2 + N3 + N4) {
        int j = i - N1 - N2 - N3; wv[j] = __float2half_rn(Wv[j]);
    } else if (i < N1 + N2 + N3 + N4 + N5) {
        int j = i - N1 - N2 - N3 - N4; wp[j] = __float2half_rn(Wp[j]);
    }
}

// ============================================================================
// proj: C[128x128] = (Ah+Al) @ B16^T, K = 512 per CTA (8 chunks of 64).
// Grid: 0..31 up (mt8 x n2 x kh2), 32..287 vp (mt32 x n2 x kh4). 2 CTAs/SM.
// ============================================================================
__global__ void __launch_bounds__(256, 2) proj_mma(
    const __half* __restrict__ uh, const __half* __restrict__ ul,
    const __half* __restrict__ vh, const __half* __restrict__ vl,
    const __half* __restrict__ wu, const __half* __restrict__ wv,
    float* __restrict__ up_part, float* __restrict__ vp_part)
{
    extern __shared__ char dsm[];
    uint32_t sb_raw = smem_u32(dsm);
    uint32_t sb = (sb_raw + 1023u) & ~1023u;

    constexpr uint32_t BUF = 49152, OFF_AL = 16384, OFF_B = 32768;

    const int bid = blockIdx.x;
    const int tid = threadIdx.x;
    const int wid = tid >> 5, lane = tid & 31;
    const int wm = (wid >> 2) * 64, wn = (wid & 3) * 32;

    const __half *Ah, *Al, *B; float* C;
    int lda, ldb;
    if (bid < 32) {
        int mt = bid >> 2, n0 = (bid >> 1) & 1, kh = bid & 1;
        Ah = uh + (size_t)mt * 128 * 1024 + kh * 512;
        Al = ul + (size_t)mt * 128 * 1024 + kh * 512; lda = 1024;
        B = wu + (size_t)n0 * 128 * 1024 + kh * 512; ldb = 1024;
        C = up_part + (size_t)kh * 1024 * 256 + (size_t)mt * 128 * 256 + n0 * 128;
    } else {
        int b2 = bid - 32;
        int mt = b2 >> 3, n0 = (b2 >> 2) & 1, kh = b2 & 3;
        Ah = vh + (size_t)mt * 128 * 2048 + kh * 512;
        Al = vl + (size_t)mt * 128 * 2048 + kh * 512; lda = 2048;
        B = wv + (size_t)n0 * 128 * 2048 + kh * 512; ldb = 2048;
        C = vp_part + (size_t)kh * 4096 * 256 + (size_t)mt * 128 * 256 + n0 * 128;
    }

    const int row = tid >> 1, seg = tid & 1;
    const __half* pAh = Ah + (size_t)row * lda + seg * 32;
    const __half* pAl = Al + (size_t)row * lda + seg * 32;
    const __half* pB  = B  + (size_t)row * ldb + seg * 32;
    const uint32_t rowoff = (uint32_t)(row * 128 + seg * 64);

    float c[4][4][4];
#pragma unroll
    for (int i = 0; i < 4; i++)
#pragma unroll
        for (int j = 0; j < 4; j++)
#pragma unroll
            for (int q = 0; q < 4; q++) c[i][j][q] = 0.f;

    auto issue = [&](int kc, int bf) {
        uint32_t base = sb + (uint32_t)bf * BUF;
#pragma unroll
        for (int j = 0; j < 4; j++) {
            uint32_t sw = SWZ(rowoff + j * 16);
            cp16(base + sw,          pAh + kc * 64 + j * 8);
            cp16(base + OFF_AL + sw, pAl + kc * 64 + j * 8);
            cp16(base + OFF_B + sw,  pB  + kc * 64 + j * 8);
        }
    };
    auto mmas = [&](int bf) {
        uint32_t base = sb + (uint32_t)bf * BUF;
#pragma unroll
        for (int ks = 0; ks < 4; ks++) {
            uint32_t ah[4][4], al[4][4], bh[4][2];
            const uint32_t acol = (uint32_t)(ks * 32 + (lane >> 4) * 16);
#pragma unroll
            for (int mi = 0; mi < 4; mi++) {
                uint32_t ro = (uint32_t)((wm + mi * 16 + (lane & 15)) * 128) + acol;
                ldsm4(ah[mi][0], ah[mi][1], ah[mi][2], ah[mi][3], base + SWZ(ro));
                ldsm4(al[mi][0], al[mi][1], al[mi][2], al[mi][3], base + OFF_AL + SWZ(ro));
            }
#pragma unroll
            for (int np = 0; np < 2; np++) {
                uint32_t ro = (uint32_t)((wn + np * 16 + (lane & 15)) * 128) + acol;
                uint32_t m0, m1, m2, m3;
                ldsm4(m0, m1, m2, m3, base + OFF_B + SWZ(ro));
                bh[2 * np][0] = m0; bh[2 * np][1] = m2;
                bh[2 * np + 1][0] = m1; bh[2 * np + 1][1] = m3;
            }
#pragma unroll
            for (int mi = 0; mi < 4; mi++)
#pragma unroll
                for (int nj = 0; nj < 4; nj++) {
                    mma_f16(c[mi][nj], ah[mi], bh[nj]);
                    mma_f16(c[mi][nj], al[mi], bh[nj]);
                }
        }
    };

    issue(0, 0); cp_commit();
    for (int kc = 0; kc < 8; kc++) {
        if (kc < 7) { issue(kc + 1, (kc + 1) & 1); cp_commit(); cp_wait<1>(); }
        else cp_wait<0>();
        __syncthreads();
        mmas(kc & 1);
        __syncthreads();
    }

    const int rin = lane >> 2, cin = (lane & 3) * 2;
#pragma unroll
    for (int mi = 0; mi < 4; mi++)
#pragma unroll
        for (int nj = 0; nj < 4; nj++) {
            float* p0 = C + (size_t)(wm + mi * 16 + rin) * 256 + wn + nj * 8 + cin;
            *(float2*)p0 = make_float2(c[mi][nj][0], c[mi][nj][1]);
            *(float2*)(p0 + 8 * 256) = make_float2(c[mi][nj][2], c[mi][nj][3]);
        }
}

// -------------------- add: vp16 = fp16(sum4), up = sum2 ----------------------
__global__ void __launch_bounds__(256) add_parts(
    const float* __restrict__ vpp, const float* __restrict__ upp,
    __half* __restrict__ vp16, float* __restrict__ up)
{
    const int NV4 = 4096 * 256 / 4;  // 262144 thread-slots for vp
    int idx = blockIdx.x * 256 + threadIdx.x;
    if (idx < NV4) {
        size_t i = (size_t)idx * 4;
        float4 a = *(const float4*)(vpp + i);
        float4 b = *(const float4*)(vpp + (size_t)4096 * 256 + i);
        float4 d = *(const float4*)(vpp + (size_t)2 * 4096 * 256 + i);
        float4 e = *(const float4*)(vpp + (size_t)3 * 4096 * 256 + i);
        __half2 h0 = __floats2half2_rn(a.x + b.x + d.x + e.x, a.y + b.y + d.y + e.y);
        __half2 h1 = __floats2half2_rn(a.z + b.z + d.z + e.z, a.w + b.w + d.w + e.w);
        uint2 o; o.x = *(uint32_t*)&h0; o.y = *(uint32_t*)&h1;
        *(uint2*)(vp16 + i) = o;
    } else if (idx < NV4 + 1024 * 256 / 4) {
        size_t i = (size_t)(idx - NV4) * 4;
        float4 a = *(const float4*)(upp + i);
        float4 b = *(const float4*)(upp + (size_t)1024 * 256 + i);
        a.x += b.x; a.y += b.y; a.z += b.z; a.w += b.w;
        *(float4*)(up + i) = a;
    }
}

// ============================================================================
// fuse: out[bm] = relu((vp16[b] ⊙ up16[bm]) @ Wp16^T + bp), 128 x 256, K=256.
// Grid 128 CTAs x 8 bm. Wp resident (128KB) + A resident (64KB) = 192.5KB.
// Warp tiles 64x64 (2x4 grid). MMA loop barrier-free.
// ============================================================================
__global__ void __launch_bounds__(256, 1) fuse_mma(
    const float* __restrict__ up, const __half* __restrict__ vp16,
    const __half* __restrict__ wp, const float* __restrict__ bp,
    float* __restrict__ out)
{
    extern __shared__ char dsm[];
    uint32_t sb_raw = smem_u32(dsm);
    uint32_t sb = (sb_raw + 1023u) & ~1023u;
    char* smp = dsm + (sb - sb_raw);

    constexpr uint32_t OFF_B = 65536;        // 4 x 32768 (256 rows x 64k)
    constexpr uint32_t OFF_UPS = 196608;     // 512B

    const int tid = threadIdx.x;
    const int wid = tid >> 5, lane = tid & 31;
    const int wm = (wid >> 2) * 64, wn = (wid & 3) * 64;

    // ---- load Wp16 once (256 rows x 256 k, 4 swizzled 64k-chunk tiles) ----
    {
        const __half* src = wp + (size_t)tid * 256;
#pragma unroll
        for (int kc = 0; kc < 4; kc++)
#pragma unroll
            for (int j = 0; j < 8; j++)
                cp16(sb + OFF_B + kc * 32768 + SWZ((uint32_t)(tid * 128 + j * 16)),
                     src + kc * 64 + j * 8);
        cp_commit();
    }

    __half2* ups2 = (__half2*)(smp + OFF_UPS);
    const int row = tid >> 1, seg = tid & 1;
    const uint32_t rowoff = (uint32_t)(row * 128 + seg * 64);

    const int bm0 = blockIdx.x * 8;

    for (int it = 0; it < 8; it++) {
        const int bm = bm0 + it, b = bm >> 5;

        __syncthreads();   // previous bm's MMA/epilogue reads done
        if (tid < 128) {
            float2 f = *(const float2*)(up + (size_t)bm * 256 + 2 * tid);
            ups2[tid] = __floats2half2_rn(f.x, f.y);
        }
        if (it == 0) cp_wait<0>();
        __syncthreads();   // ups2 visible (and B resident on first iter)

        // ---- build A resident: A[r,k] = vp16[b*128+r,k] * up16[bm,k] ----
        {
            const __half* vrow = vp16 + (size_t)(b * 128 + row) * 256 + seg * 32;
#pragma unroll
            for (int kc = 0; kc < 4; kc++) {
                char* dstc = smp + kc * 16384;
#pragma unroll
                for (int j = 0; j < 4; j++) {
                    uint4 x = *(const uint4*)(vrow + kc * 64 + j * 8);
                    const __half2* m = &ups2[kc * 32 + seg * 16 + j * 4];
                    *(__half2*)&x.x = __hmul2(*(__half2*)&x.x, m[0]);
                    *(__half2*)&x.y = __hmul2(*(__half2*)&x.y, m[1]);
                    *(__half2*)&x.z = __hmul2(*(__half2*)&x.z, m[2]);
                    *(__half2*)&x.w = __hmul2(*(__half2*)&x.w, m[3]);
                    *(uint4*)(dstc + SWZ(rowoff + j * 16)) = x;
                }
            }
        }
        __syncthreads();   // A ready

        float c[4][8][4];
#pragma unroll
        for (int i = 0; i < 4; i++)
#pragma unroll
            for (int j = 0; j < 8; j++)
#pragma unroll
                for (int q = 0; q < 4; q++) c[i][j][q] = 0.f;

        // ---- barrier-free MMA loop: 16 k-steps ----
#pragma unroll
        for (int chunk = 0; chunk < 4; chunk++) {
            uint32_t abase = sb + (uint32_t)chunk * 16384;
            uint32_t bbase = sb + OFF_B + (uint32_t)chunk * 32768;
#pragma unroll
            for (int ks = 0; ks < 4; ks++) {
                uint32_t af[4][4], bf[8][2];
                const uint32_t acol = (uint32_t)(ks * 32 + (lane >> 4) * 16);
#pragma unroll
                for (int mi = 0; mi < 4; mi++) {
                    uint32_t ro = (uint32_t)((wm + mi * 16 + (lane & 15)) * 128) + acol;
                    ldsm4(af[mi][0], af[mi][1], af[mi][2], af[mi][3], abase + SWZ(ro));
                }
#pragma unroll
                for (int np = 0; np < 4; np++) {
                    uint32_t ro = (uint32_t)((wn + np * 16 + (lane & 15)) * 128) + acol;
                    uint32_t m0, m1, m2, m3;
                    ldsm4(m0, m1, m2, m3, bbase + SWZ(ro));
                    bf[2 * np][0] = m0; bf[2 * np][1] = m2;
                    bf[2 * np + 1][0] = m1; bf[2 * np + 1][1] = m3;
                }
#pragma unroll
                for (int mi = 0; mi < 4; mi++)
#pragma unroll
                    for (int nj = 0; nj < 8; nj++)
                        mma_f16(c[mi][nj], af[mi], bf[nj]);
            }
        }

        // ---- epilogue: +bias, relu, store ----
        const int rin = lane >> 2, cin = (lane & 3) * 2;
        float* obase = out + (size_t)bm * 128 * 256;
#pragma unroll
        for (int nj = 0; nj < 8; nj++) {
            const int f = wn + nj * 8 + cin;
            const float b0 = bp[f], b1 = bp[f + 1];
#pragma unroll
            for (int mi = 0; mi < 4; mi++) {
                float* p0 = obase + (size_t)(wm + mi * 16 + rin) * 256 + f;
                *(float2*)p0 = make_float2(fmaxf(c[mi][nj][0] + b0, 0.f),
                                           fmaxf(c[mi][nj][1] + b1, 0.f));
                *(float2*)(p0 + 8 * 256) = make_float2(fmaxf(c[mi][nj][2] + b0, 0.f),
                                                       fmaxf(c[mi][nj][3] + b1, 0.f));
            }
        }
    }
}

// -------------------- host launch -------------------------------------------
extern "C" void kernel_launch(void* const* d_in, const int* in_sizes, int n_in,
                              void* d_out, int out_size) {
    const float* u  = (const float*)d_in[0];   // (32,32,1024)
    const float* v  = (const float*)d_in[1];   // (32,128,2048)
    const float* Wu = (const float*)d_in[2];   // (256,1024)
    const float* Wv = (const float*)d_in[3];   // (256,2048)
    const float* Wp = (const float*)d_in[4];   // (256,256)
    const float* bp = (const float*)d_in[5];   // (256,)
    float* out = (float*)d_out;                // (32,32,128,256)

    float *up_p, *upp_p, *vpp_p;
    __half *vp16, *uh, *ul, *vh, *vl, *wu, *wv, *wp;
    cudaGetSymbolAddress((void**)&up_p, g_up);
    cudaGetSymbolAddress((void**)&upp_p, g_up_part);
    cudaGetSymbolAddress((void**)&vpp_p, g_vp_part);
    cudaGetSymbolAddress((void**)&vp16, g_vp16);
    cudaGetSymbolAddress((void**)&uh, g_uh);
    cudaGetSymbolAddress((void**)&ul, g_ul);
    cudaGetSymbolAddress((void**)&vh, g_vh);
    cudaGetSymbolAddress((void**)&vl, g_vl);
    cudaGetSymbolAddress((void**)&wu, g_wu16);
    cudaGetSymbolAddress((void**)&wv, g_wv16);
    cudaGetSymbolAddress((void**)&wp, g_wp16);

    const int PROJ_SMEM = 2 * 49152 + 1024;          // 99328
    const int FUSE_SMEM = 196608 + 512 + 1024;       // 198144
    cudaFuncSetAttribute(proj_mma, cudaFuncAttributeMaxDynamicSharedMemorySize, PROJ_SMEM);
    cudaFuncSetAttribute(fuse_mma, cudaFuncAttributeMaxDynamicSharedMemorySize, FUSE_SMEM);

    const int total = 1024 * 1024 + 4096 * 2048 + 256 * 1024 + 256 * 2048 + 256 * 256;
    prep_cvt<<<(total + 255) / 256, 256>>>(u, v, Wu, Wv, Wp, uh, ul, vh, vl, wu, wv, wp);
    proj_mma<<<288, 256, PROJ_SMEM>>>(uh, ul, vh, vl, wu, wv, upp_p, vpp_p);
    add_parts<<<1280, 256>>>(vpp_p, upp_p, vp16, up_p);
    fuse_mma<<<128, 256, FUSE_SMEM>>>(up_p, vp16, wp, bp, out);
}

// round 10
// speedup vs baseline: 1.5050x; 1.5050x over previous
#include <cuda_runtime.h>
#include <cuda_fp16.h>
#include <cstdint>

// ============================================================================
// LowRankBilinearFusion, HMMA fp16, single-product proj, resident-B fuse:
//   prep: u,v,Wu,Wv,Wp -> fp16
//   proj: up16 = u@Wu^T (direct fp16 out); vp_part = v@Wv^T k-split x2 (fp32)
//   add:  vp16 = fp16(part0+part1)
//   fuse: out[bm,n0] = relu((vp16[b] ⊙ up16[bm]) @ Wp16[n0]^T + bp)
//         grid (1024,2); 128 thr, 4 warps, 64x64 tiles; B resident 64KB;
//         A double-buffered (1 sync/chunk); 2 CTAs/SM.
// ============================================================================

__device__ float  g_vp_part[2 * 4096 * 256];
__device__ __half g_up16[1024 * 256];
__device__ __half g_vp16[4096 * 256];
__device__ __half g_u16[1024 * 1024];
__device__ __half g_v16[4096 * 2048];
__device__ __half g_wu16[256 * 1024];
__device__ __half g_wv16[256 * 2048];
__device__ __half g_wp16[256 * 256];

#define SWZ(o) ((o) ^ (((o) >> 3) & 0x70))

__device__ __forceinline__ uint32_t smem_u32(const void* p) {
    uint32_t a;
    asm("{ .reg .u64 t; cvta.to.shared.u64 t, %1; cvt.u32.u64 %0, t; }" : "=r"(a) : "l"(p));
    return a;
}
__device__ __forceinline__ void ldsm4(uint32_t& r0, uint32_t& r1, uint32_t& r2, uint32_t& r3,
                                      uint32_t addr) {
    asm volatile("ldmatrix.sync.aligned.m8n8.x4.shared.b16 {%0,%1,%2,%3}, [%4];"
                 : "=r"(r0), "=r"(r1), "=r"(r2), "=r"(r3) : "r"(addr));
}
__device__ __forceinline__ void mma_f16(float* c, const uint32_t* a, const uint32_t* b) {
    asm volatile(
        "mma.sync.aligned.m16n8k16.row.col.f32.f16.f16.f32 "
        "{%0,%1,%2,%3}, {%4,%5,%6,%7}, {%8,%9}, {%0,%1,%2,%3};"
        : "+f"(c[0]), "+f"(c[1]), "+f"(c[2]), "+f"(c[3])
        : "r"(a[0]), "r"(a[1]), "r"(a[2]), "r"(a[3]), "r"(b[0]), "r"(b[1]));
}
__device__ __forceinline__ void cp16(uint32_t dst, const void* src) {
    asm volatile("cp.async.cg.shared.global [%0], [%1], 16;" :: "r"(dst), "l"(src));
}
__device__ __forceinline__ void cp_commit() { asm volatile("cp.async.commit_group;" ::: "memory"); }
template <int N>
__device__ __forceinline__ void cp_wait() { asm volatile("cp.async.wait_group %0;" :: "n"(N) : "memory"); }

// -------------------- prep: convert all operands to fp16 ---------------------
__global__ void __launch_bounds__(256) prep_cvt(
    const float* __restrict__ u, const float* __restrict__ v,
    const float* __restrict__ Wu, const float* __restrict__ Wv, const float* __restrict__ Wp,
    __half* u16, __half* v16, __half* wu, __half* wv, __half* wp)
{
    const int N1 = 1024 * 1024, N2 = 4096 * 2048;
    const int N3 = 256 * 1024, N4 = 256 * 2048, N5 = 256 * 256;
    int t = blockIdx.x * 256 + threadIdx.x;
    size_t i = (size_t)t * 4;
    const float* src; __half* dst; size_t j;
    if (i < N1)                          { src = u;  dst = u16; j = i; }
    else if (i < (size_t)N1 + N2)        { src = v;  dst = v16; j = i - N1; }
    else if (i < (size_t)N1 + N2 + N3)   { src = Wu; dst = wu;  j = i - N1 - N2; }
    else if (i < (size_t)N1 + N2 + N3 + N4) { src = Wv; dst = wv; j = i - N1 - N2 - N3; }
    else if (i < (size_t)N1 + N2 + N3 + N4 + N5) { src = Wp; dst = wp; j = i - N1 - N2 - N3 - N4; }
    else return;
    float4 x = *(const float4*)(src + j);
    __half2 h0 = __floats2half2_rn(x.x, x.y);
    __half2 h1 = __floats2half2_rn(x.z, x.w);
    uint2 o; o.x = *(uint32_t*)&h0; o.y = *(uint32_t*)&h1;
    *(uint2*)(dst + j) = o;
}

// ============================================================================
// proj: C[128x128] = A16 @ B16^T, K = 1024 per CTA (16 chunks of 64).
// Grid: 0..15 up (mt8 x n2, K=1024) -> up16 direct;
//       16..143 vp (mt32 x n2 x kh2, K=1024) -> fp32 partials.
// 256 thr, 8 warps 2x4, warp tile 64x32. 2 CTAs/SM.
// ============================================================================
__global__ void __launch_bounds__(256, 2) proj_mma(
    const __half* __restrict__ u16, const __half* __restrict__ v16,
    const __half* __restrict__ wu, const __half* __restrict__ wv,
    __half* __restrict__ up16, float* __restrict__ vp_part)
{
    extern __shared__ char dsm[];
    uint32_t sb_raw = smem_u32(dsm);
    uint32_t sb = (sb_raw + 1023u) & ~1023u;

    constexpr uint32_t BUF = 32768, OFF_B = 16384;

    const int bid = blockIdx.x;
    const int tid = threadIdx.x;
    const int wid = tid >> 5, lane = tid & 31;
    const int wm = (wid >> 2) * 64, wn = (wid & 3) * 32;

    const __half *A, *B;
    int lda, ldb;
    bool is_up;
    __half* Ch = nullptr; float* Cf = nullptr;
    if (bid < 16) {
        int mt = bid >> 1, n0 = bid & 1;
        A = u16 + (size_t)mt * 128 * 1024; lda = 1024;
        B = wu + (size_t)n0 * 128 * 1024; ldb = 1024;
        Ch = up16 + (size_t)mt * 128 * 256 + n0 * 128;
        is_up = true;
    } else {
        int b2 = bid - 16;
        int mt = b2 >> 2, n0 = (b2 >> 1) & 1, kh = b2 & 1;
        A = v16 + (size_t)mt * 128 * 2048 + kh * 1024; lda = 2048;
        B = wv + (size_t)n0 * 128 * 2048 + kh * 1024; ldb = 2048;
        Cf = vp_part + (size_t)kh * 4096 * 256 + (size_t)mt * 128 * 256 + n0 * 128;
        is_up = false;
    }

    const int row = tid >> 1, seg = tid & 1;
    const __half* pA = A + (size_t)row * lda + seg * 32;
    const __half* pB = B + (size_t)row * ldb + seg * 32;
    const uint32_t rowoff = (uint32_t)(row * 128 + seg * 64);

    float c[4][4][4];
#pragma unroll
    for (int i = 0; i < 4; i++)
#pragma unroll
        for (int j = 0; j < 4; j++)
#pragma unroll
            for (int q = 0; q < 4; q++) c[i][j][q] = 0.f;

    auto issue = [&](int kc, int bf) {
        uint32_t base = sb + (uint32_t)bf * BUF;
#pragma unroll
        for (int j = 0; j < 4; j++) {
            uint32_t sw = SWZ(rowoff + j * 16);
            cp16(base + sw,         pA + kc * 64 + j * 8);
            cp16(base + OFF_B + sw, pB + kc * 64 + j * 8);
        }
    };
    auto mmas = [&](int bf) {
        uint32_t base = sb + (uint32_t)bf * BUF;
#pragma unroll
        for (int ks = 0; ks < 4; ks++) {
            uint32_t a[4][4], bfr[4][2];
            const uint32_t acol = (uint32_t)(ks * 32 + (lane >> 4) * 16);
#pragma unroll
            for (int mi = 0; mi < 4; mi++) {
                uint32_t ro = (uint32_t)((wm + mi * 16 + (lane & 15)) * 128) + acol;
                ldsm4(a[mi][0], a[mi][1], a[mi][2], a[mi][3], base + SWZ(ro));
            }
#pragma unroll
            for (int np = 0; np < 2; np++) {
                uint32_t ro = (uint32_t)((wn + np * 16 + (lane & 15)) * 128) + acol;
                uint32_t m0, m1, m2, m3;
                ldsm4(m0, m1, m2, m3, base + OFF_B + SWZ(ro));
                bfr[2 * np][0] = m0; bfr[2 * np][1] = m2;
                bfr[2 * np + 1][0] = m1; bfr[2 * np + 1][1] = m3;
            }
#pragma unroll
            for (int mi = 0; mi < 4; mi++)
#pragma unroll
                for (int nj = 0; nj < 4; nj++)
                    mma_f16(c[mi][nj], a[mi], bfr[nj]);
        }
    };

    issue(0, 0); cp_commit();
    for (int kc = 0; kc < 16; kc++) {
        if (kc < 15) { issue(kc + 1, (kc + 1) & 1); cp_commit(); cp_wait<1>(); }
        else cp_wait<0>();
        __syncthreads();
        mmas(kc & 1);
        __syncthreads();
    }

    const int rin = lane >> 2, cin = (lane & 3) * 2;
    if (is_up) {
#pragma unroll
        for (int mi = 0; mi < 4; mi++)
#pragma unroll
            for (int nj = 0; nj < 4; nj++) {
                __half* p0 = Ch + (size_t)(wm + mi * 16 + rin) * 256 + wn + nj * 8 + cin;
                __half2 h0 = __floats2half2_rn(c[mi][nj][0], c[mi][nj][1]);
                __half2 h1 = __floats2half2_rn(c[mi][nj][2], c[mi][nj][3]);
                *(__half2*)p0 = h0;
                *(__half2*)(p0 + 8 * 256) = h1;
            }
    } else {
#pragma unroll
        for (int mi = 0; mi < 4; mi++)
#pragma unroll
            for (int nj = 0; nj < 4; nj++) {
                float* p0 = Cf + (size_t)(wm + mi * 16 + rin) * 256 + wn + nj * 8 + cin;
                *(float2*)p0 = make_float2(c[mi][nj][0], c[mi][nj][1]);
                *(float2*)(p0 + 8 * 256) = make_float2(c[mi][nj][2], c[mi][nj][3]);
            }
    }
}

// -------------------- add: vp16 = fp16(part0 + part1) ------------------------
__global__ void __launch_bounds__(256) add_parts(
    const float* __restrict__ vpp, __half* __restrict__ vp16)
{
    size_t i = ((size_t)blockIdx.x * 256 + threadIdx.x) * 4;
    float4 a = *(const float4*)(vpp + i);
    float4 b = *(const float4*)(vpp + (size_t)4096 * 256 + i);
    __half2 h0 = __floats2half2_rn(a.x + b.x, a.y + b.y);
    __half2 h1 = __floats2half2_rn(a.z + b.z, a.w + b.w);
    uint2 o; o.x = *(uint32_t*)&h0; o.y = *(uint32_t*)&h1;
    *(uint2*)(vp16 + i) = o;
}

// ============================================================================
// fuse: out[bm, n0] = relu((vp16[b] ⊙ up16[bm]) @ Wp16[n0]^T + bp)
// 128 x 128 per CTA, K=256. 128 threads, 4 warps (2x2), warp tile 64x64.
// Each thread owns one FULL 128B A row: loadA/storeA sweep j<8 (the R9 bug
// was j<4 here -> upper half of A uninitialized -> inf).
// B resident (4 x 16KB, cp.async once). A double-buffered (2 x 16KB).
// 2 CTAs/SM.
// ============================================================================
__global__ void __launch_bounds__(128, 2) fuse_mma(
    const __half* __restrict__ up16, const __half* __restrict__ vp16,
    const __half* __restrict__ wp, const float* __restrict__ bp,
    float* __restrict__ out)
{
    extern __shared__ char dsm[];
    uint32_t sb_raw = smem_u32(dsm);
    uint32_t sb = (sb_raw + 1023u) & ~1023u;
    char* smp = dsm + (sb - sb_raw);

    constexpr uint32_t OFF_A = 65536, ABUF = 16384, OFF_UPS = 98304;

    const int bm = blockIdx.x, b = bm >> 5;
    const int n0 = blockIdx.y;
    const int tid = threadIdx.x;
    const int wid = tid >> 5, lane = tid & 31;
    const int wm = (wid >> 1) * 64, wn = (wid & 1) * 64;

    const int row = tid;  // 128 threads -> one full 128B row each
    const uint32_t rowoff = (uint32_t)(row * 128);

    // ---- B: all 4 chunks of Wp16[n0] resident via cp.async (64KB) ----
    {
        const __half* wrow = wp + (size_t)(n0 * 128 + row) * 256;
#pragma unroll
        for (int kc = 0; kc < 4; kc++)
#pragma unroll
            for (int j = 0; j < 8; j++)
                cp16(sb + kc * 16384 + SWZ(rowoff + j * 16), wrow + kc * 64 + j * 8);
        cp_commit();
    }

    // ---- up16[bm] -> smem half2 ----
    __half2* ups2 = (__half2*)(smp + OFF_UPS);
    ups2[tid] = ((const __half2*)(up16 + (size_t)bm * 256))[tid];
    __syncthreads();   // ups2 visible

    const __half* vrow = vp16 + (size_t)(b * 128 + row) * 256;

    uint4 xa[8];
    auto loadA = [&](int kc) {
#pragma unroll
        for (int j = 0; j < 8; j++) xa[j] = *(const uint4*)(vrow + kc * 64 + j * 8);
    };
    auto storeA = [&](int kc, int bf) {
        char* p = smp + OFF_A + (uint32_t)bf * ABUF;
#pragma unroll
        for (int j = 0; j < 8; j++) {
            uint4 x = xa[j];
            const __half2* m = &ups2[kc * 32 + j * 4];
            *(__half2*)&x.x = __hmul2(*(__half2*)&x.x, m[0]);
            *(__half2*)&x.y = __hmul2(*(__half2*)&x.y, m[1]);
            *(__half2*)&x.z = __hmul2(*(__half2*)&x.z, m[2]);
            *(__half2*)&x.w = __hmul2(*(__half2*)&x.w, m[3]);
            *(uint4*)(p + SWZ(rowoff + j * 16)) = x;
        }
    };

    float c[4][8][4];
#pragma unroll
    for (int i = 0; i < 4; i++)
#pragma unroll
        for (int j = 0; j < 8; j++)
#pragma unroll
            for (int q = 0; q < 4; q++) c[i][j][q] = 0.f;

    loadA(0);
    storeA(0, 0);
    cp_wait<0>();      // B resident
    __syncthreads();   // A0 + B visible

    for (int kc = 0; kc < 4; kc++) {
        if (kc < 3) loadA(kc + 1);

        uint32_t abase = sb + OFF_A + (uint32_t)(kc & 1) * ABUF;
        uint32_t bbase = sb + (uint32_t)kc * 16384;
#pragma unroll
        for (int ks = 0; ks < 4; ks++) {
            uint32_t af[4][4], bf[8][2];
            const uint32_t acol = (uint32_t)(ks * 32 + (lane >> 4) * 16);
#pragma unroll
            for (int mi = 0; mi < 4; mi++) {
                uint32_t ro = (uint32_t)((wm + mi * 16 + (lane & 15)) * 128) + acol;
                ldsm4(af[mi][0], af[mi][1], af[mi][2], af[mi][3], abase + SWZ(ro));
            }
#pragma unroll
            for (int np = 0; np < 4; np++) {
                uint32_t ro = (uint32_t)((wn + np * 16 + (lane & 15)) * 128) + acol;
                uint32_t m0, m1, m2, m3;
                ldsm4(m0, m1, m2, m3, bbase + SWZ(ro));
                bf[2 * np][0] = m0; bf[2 * np][1] = m2;
                bf[2 * np + 1][0] = m1; bf[2 * np + 1][1] = m3;
            }
#pragma unroll
            for (int mi = 0; mi < 4; mi++)
#pragma unroll
                for (int nj = 0; nj < 8; nj++)
                    mma_f16(c[mi][nj], af[mi], bf[nj]);
        }

        if (kc < 3) {
            storeA(kc + 1, (kc + 1) & 1);
            __syncthreads();
        }
    }

    // ---- epilogue: +bias, relu, store ----
    const int rin = lane >> 2, cin = (lane & 3) * 2;
    float* obase = out + (size_t)bm * 128 * 256 + n0 * 128;
#pragma unroll
    for (int nj = 0; nj < 8; nj++) {
        const int f = wn + nj * 8 + cin;
        const float b0 = bp[n0 * 128 + f], b1 = bp[n0 * 128 + f + 1];
#pragma unroll
        for (int mi = 0; mi < 4; mi++) {
            float* p0 = obase + (size_t)(wm + mi * 16 + rin) * 256 + f;
            *(float2*)p0 = make_float2(fmaxf(c[mi][nj][0] + b0, 0.f),
                                       fmaxf(c[mi][nj][1] + b1, 0.f));
            *(float2*)(p0 + 8 * 256) = make_float2(fmaxf(c[mi][nj][2] + b0, 0.f),
                                                   fmaxf(c[mi][nj][3] + b1, 0.f));
        }
    }
}

// -------------------- host launch -------------------------------------------
extern "C" void kernel_launch(void* const* d_in, const int* in_sizes, int n_in,
                              void* d_out, int out_size) {
    const float* u  = (const float*)d_in[0];   // (32,32,1024)
    const float* v  = (const float*)d_in[1];   // (32,128,2048)
    const float* Wu = (const float*)d_in[2];   // (256,1024)
    const float* Wv = (const float*)d_in[3];   // (256,2048)
    const float* Wp = (const float*)d_in[4];   // (256,256)
    const float* bp = (const float*)d_in[5];   // (256,)
    float* out = (float*)d_out;                // (32,32,128,256)

    float* vpp_p;
    __half *up16, *vp16, *u16, *v16, *wu, *wv, *wp;
    cudaGetSymbolAddress((void**)&vpp_p, g_vp_part);
    cudaGetSymbolAddress((void**)&up16, g_up16);
    cudaGetSymbolAddress((void**)&vp16, g_vp16);
    cudaGetSymbolAddress((void**)&u16, g_u16);
    cudaGetSymbolAddress((void**)&v16, g_v16);
    cudaGetSymbolAddress((void**)&wu, g_wu16);
    cudaGetSymbolAddress((void**)&wv, g_wv16);
    cudaGetSymbolAddress((void**)&wp, g_wp16);

    const int PROJ_SMEM = 2 * 32768 + 1024;          // 66560
    const int FUSE_SMEM = 98304 + 512 + 1024;        // 99840
    cudaFuncSetAttribute(proj_mma, cudaFuncAttributeMaxDynamicSharedMemorySize, PROJ_SMEM);
    cudaFuncSetAttribute(fuse_mma, cudaFuncAttributeMaxDynamicSharedMemorySize, FUSE_SMEM);

    const int total = 1024 * 1024 + 4096 * 2048 + 256 * 1024 + 256 * 2048 + 256 * 256;
    prep_cvt<<<(total / 4 + 255) / 256, 256>>>(u, v, Wu, Wv, Wp, u16, v16, wu, wv, wp);
    proj_mma<<<144, 256, PROJ_SMEM>>>(u16, v16, wu, wv, up16, vpp_p);
    add_parts<<<1024, 256>>>(vpp_p, vp16);
    fuse_mma<<<dim3(1024, 2), 128, FUSE_SMEM>>>(up16, vp16, wp, bp, out);
}

// round 11
// speedup vs baseline: 1.9331x; 1.2845x over previous
#include <cuda_runtime.h>
#include <cuda_fp16.h>
#include <cstdint>

// ============================================================================
// LowRankBilinearFusion, HMMA fp16:
//   prep: u,v,Wu,Wv,Wp -> fp16
//   proj: up16 = u@Wu^T (direct fp16 out); vp_part = v@Wv^T k-split x2 (fp32)
//   add:  vp16 = fp16(part0+part1)
//   fuse: out[bm,n0] = relu((vp16[b] ⊙ up16[bm]) @ Wp16[n0]^T + bp)
//     256 thr, 8 warps (2x4), warp tile 64x32, 2 CTAs/SM.
//     A = RAW vp16, fully smem-resident (64KB, cp.async once); the up16
//     multiply is applied to A FRAGMENTS in registers (per-lane k mapping),
//     so there is no A build phase at all. B double-buffered 2x16KB.
// ============================================================================

__device__ float  g_vp_part[2 * 4096 * 256];
__device__ __half g_up16[1024 * 256];
__device__ __half g_vp16[4096 * 256];
__device__ __half g_u16[1024 * 1024];
__device__ __half g_v16[4096 * 2048];
__device__ __half g_wu16[256 * 1024];
__device__ __half g_wv16[256 * 2048];
__device__ __half g_wp16[256 * 256];

#define SWZ(o) ((o) ^ (((o) >> 3) & 0x70))

__device__ __forceinline__ uint32_t smem_u32(const void* p) {
    uint32_t a;
    asm("{ .reg .u64 t; cvta.to.shared.u64 t, %1; cvt.u32.u64 %0, t; }" : "=r"(a) : "l"(p));
    return a;
}
__device__ __forceinline__ void ldsm4(uint32_t& r0, uint32_t& r1, uint32_t& r2, uint32_t& r3,
                                      uint32_t addr) {
    asm volatile("ldmatrix.sync.aligned.m8n8.x4.shared.b16 {%0,%1,%2,%3}, [%4];"
                 : "=r"(r0), "=r"(r1), "=r"(r2), "=r"(r3) : "r"(addr));
}
__device__ __forceinline__ void mma_f16(float* c, const uint32_t* a, const uint32_t* b) {
    asm volatile(
        "mma.sync.aligned.m16n8k16.row.col.f32.f16.f16.f32 "
        "{%0,%1,%2,%3}, {%4,%5,%6,%7}, {%8,%9}, {%0,%1,%2,%3};"
        : "+f"(c[0]), "+f"(c[1]), "+f"(c[2]), "+f"(c[3])
        : "r"(a[0]), "r"(a[1]), "r"(a[2]), "r"(a[3]), "r"(b[0]), "r"(b[1]));
}
__device__ __forceinline__ void cp16(uint32_t dst, const void* src) {
    asm volatile("cp.async.cg.shared.global [%0], [%1], 16;" :: "r"(dst), "l"(src));
}
__device__ __forceinline__ void cp_commit() { asm volatile("cp.async.commit_group;" ::: "memory"); }
template <int N>
__device__ __forceinline__ void cp_wait() { asm volatile("cp.async.wait_group %0;" :: "n"(N) : "memory"); }
__device__ __forceinline__ uint32_t hmul2u(uint32_t a, __half2 m) {
    __half2 r = __hmul2(*(__half2*)&a, m);
    return *(uint32_t*)&r;
}

// -------------------- prep: convert all operands to fp16 ---------------------
__global__ void __launch_bounds__(256) prep_cvt(
    const float* __restrict__ u, const float* __restrict__ v,
    const float* __restrict__ Wu, const float* __restrict__ Wv, const float* __restrict__ Wp,
    __half* u16, __half* v16, __half* wu, __half* wv, __half* wp)
{
    const int N1 = 1024 * 1024, N2 = 4096 * 2048;
    const int N3 = 256 * 1024, N4 = 256 * 2048, N5 = 256 * 256;
    int t = blockIdx.x * 256 + threadIdx.x;
    size_t i = (size_t)t * 4;
    const float* src; __half* dst; size_t j;
    if (i < N1)                          { src = u;  dst = u16; j = i; }
    else if (i < (size_t)N1 + N2)        { src = v;  dst = v16; j = i - N1; }
    else if (i < (size_t)N1 + N2 + N3)   { src = Wu; dst = wu;  j = i - N1 - N2; }
    else if (i < (size_t)N1 + N2 + N3 + N4) { src = Wv; dst = wv; j = i - N1 - N2 - N3; }
    else if (i < (size_t)N1 + N2 + N3 + N4 + N5) { src = Wp; dst = wp; j = i - N1 - N2 - N3 - N4; }
    else return;
    float4 x = *(const float4*)(src + j);
    __half2 h0 = __floats2half2_rn(x.x, x.y);
    __half2 h1 = __floats2half2_rn(x.z, x.w);
    uint2 o; o.x = *(uint32_t*)&h0; o.y = *(uint32_t*)&h1;
    *(uint2*)(dst + j) = o;
}

// ============================================================================
// proj: C[128x128] = A16 @ B16^T, K = 1024 per CTA (16 chunks of 64).
// Grid: 0..15 up (mt8 x n2) -> up16 direct; 16..143 vp (mt32 x n2 x kh2).
// 256 thr, 8 warps 2x4, warp tile 64x32. 2 CTAs/SM.
// ============================================================================
__global__ void __launch_bounds__(256, 2) proj_mma(
    const __half* __restrict__ u16, const __half* __restrict__ v16,
    const __half* __restrict__ wu, const __half* __restrict__ wv,
    __half* __restrict__ up16, float* __restrict__ vp_part)
{
    extern __shared__ char dsm[];
    uint32_t sb_raw = smem_u32(dsm);
    uint32_t sb = (sb_raw + 1023u) & ~1023u;

    constexpr uint32_t BUF = 32768, OFF_B = 16384;

    const int bid = blockIdx.x;
    const int tid = threadIdx.x;
    const int wid = tid >> 5, lane = tid & 31;
    const int wm = (wid >> 2) * 64, wn = (wid & 3) * 32;

    const __half *A, *B;
    int lda, ldb;
    bool is_up;
    __half* Ch = nullptr; float* Cf = nullptr;
    if (bid < 16) {
        int mt = bid >> 1, n0 = bid & 1;
        A = u16 + (size_t)mt * 128 * 1024; lda = 1024;
        B = wu + (size_t)n0 * 128 * 1024; ldb = 1024;
        Ch = up16 + (size_t)mt * 128 * 256 + n0 * 128;
        is_up = true;
    } else {
        int b2 = bid - 16;
        int mt = b2 >> 2, n0 = (b2 >> 1) & 1, kh = b2 & 1;
        A = v16 + (size_t)mt * 128 * 2048 + kh * 1024; lda = 2048;
        B = wv + (size_t)n0 * 128 * 2048 + kh * 1024; ldb = 2048;
        Cf = vp_part + (size_t)kh * 4096 * 256 + (size_t)mt * 128 * 256 + n0 * 128;
        is_up = false;
    }

    const int row = tid >> 1, seg = tid & 1;
    const __half* pA = A + (size_t)row * lda + seg * 32;
    const __half* pB = B + (size_t)row * ldb + seg * 32;
    const uint32_t rowoff = (uint32_t)(row * 128 + seg * 64);

    float c[4][4][4];
#pragma unroll
    for (int i = 0; i < 4; i++)
#pragma unroll
        for (int j = 0; j < 4; j++)
#pragma unroll
            for (int q = 0; q < 4; q++) c[i][j][q] = 0.f;

    auto issue = [&](int kc, int bf) {
        uint32_t base = sb + (uint32_t)bf * BUF;
#pragma unroll
        for (int j = 0; j < 4; j++) {
            uint32_t sw = SWZ(rowoff + j * 16);
            cp16(base + sw,         pA + kc * 64 + j * 8);
            cp16(base + OFF_B + sw, pB + kc * 64 + j * 8);
        }
    };
    auto mmas = [&](int bf) {
        uint32_t base = sb + (uint32_t)bf * BUF;
#pragma unroll
        for (int ks = 0; ks < 4; ks++) {
            uint32_t a[4][4], bfr[4][2];
            const uint32_t acol = (uint32_t)(ks * 32 + (lane >> 4) * 16);
#pragma unroll
            for (int mi = 0; mi < 4; mi++) {
                uint32_t ro = (uint32_t)((wm + mi * 16 + (lane & 15)) * 128) + acol;
                ldsm4(a[mi][0], a[mi][1], a[mi][2], a[mi][3], base + SWZ(ro));
            }
#pragma unroll
            for (int np = 0; np < 2; np++) {
                uint32_t ro = (uint32_t)((wn + np * 16 + (lane & 15)) * 128) + acol;
                uint32_t m0, m1, m2, m3;
                ldsm4(m0, m1, m2, m3, base + OFF_B + SWZ(ro));
                bfr[2 * np][0] = m0; bfr[2 * np][1] = m2;
                bfr[2 * np + 1][0] = m1; bfr[2 * np + 1][1] = m3;
            }
#pragma unroll
            for (int mi = 0; mi < 4; mi++)
#pragma unroll
                for (int nj = 0; nj < 4; nj++)
                    mma_f16(c[mi][nj], a[mi], bfr[nj]);
        }
    };

    issue(0, 0); cp_commit();
    for (int kc = 0; kc < 16; kc++) {
        if (kc < 15) { issue(kc + 1, (kc + 1) & 1); cp_commit(); cp_wait<1>(); }
        else cp_wait<0>();
        __syncthreads();
        mmas(kc & 1);
        __syncthreads();
    }

    const int rin = lane >> 2, cin = (lane & 3) * 2;
    if (is_up) {
#pragma unroll
        for (int mi = 0; mi < 4; mi++)
#pragma unroll
            for (int nj = 0; nj < 4; nj++) {
                __half* p0 = Ch + (size_t)(wm + mi * 16 + rin) * 256 + wn + nj * 8 + cin;
                __half2 h0 = __floats2half2_rn(c[mi][nj][0], c[mi][nj][1]);
                __half2 h1 = __floats2half2_rn(c[mi][nj][2], c[mi][nj][3]);
                *(__half2*)p0 = h0;
                *(__half2*)(p0 + 8 * 256) = h1;
            }
    } else {
#pragma unroll
        for (int mi = 0; mi < 4; mi++)
#pragma unroll
            for (int nj = 0; nj < 4; nj++) {
                float* p0 = Cf + (size_t)(wm + mi * 16 + rin) * 256 + wn + nj * 8 + cin;
                *(float2*)p0 = make_float2(c[mi][nj][0], c[mi][nj][1]);
                *(float2*)(p0 + 8 * 256) = make_float2(c[mi][nj][2], c[mi][nj][3]);
            }
    }
}

// -------------------- add: vp16 = fp16(part0 + part1) ------------------------
__global__ void __launch_bounds__(256) add_parts(
    const float* __restrict__ vpp, __half* __restrict__ vp16)
{
    size_t i = ((size_t)blockIdx.x * 256 + threadIdx.x) * 4;
    float4 a = *(const float4*)(vpp + i);
    float4 b = *(const float4*)(vpp + (size_t)4096 * 256 + i);
    __half2 h0 = __floats2half2_rn(a.x + b.x, a.y + b.y);
    __half2 h1 = __floats2half2_rn(a.z + b.z, a.w + b.w);
    uint2 o; o.x = *(uint32_t*)&h0; o.y = *(uint32_t*)&h1;
    *(uint2*)(vp16 + i) = o;
}

// ============================================================================
// fuse: out[bm, n0] = relu((vp16[b] ⊙ up16[bm]) @ Wp16[n0]^T + bp)
// 128 x 128 per CTA, K=256. 256 threads, 8 warps (2x4), warp tile 64x32.
// A = raw vp16 resident (4 x 16KB, cp.async once). up16 applied to A
// fragments in registers:  a0,a1 *= ups2[ksg*8 + lane%4],
//                          a2,a3 *= ups2[ksg*8 + 4 + lane%4].
// B double-buffered 2x16KB (progressive cp.async groups). 2 CTAs/SM.
// ============================================================================
__global__ void __launch_bounds__(256, 2) fuse_mma(
    const __half* __restrict__ up16, const __half* __restrict__ vp16,
    const __half* __restrict__ wp, const float* __restrict__ bp,
    float* __restrict__ out)
{
    extern __shared__ char dsm[];
    uint32_t sb_raw = smem_u32(dsm);
    uint32_t sb = (sb_raw + 1023u) & ~1023u;
    char* smp = dsm + (sb - sb_raw);

    constexpr uint32_t OFF_B = 65536, BBUF = 16384, OFF_UPS = 98304;

    const int bm = blockIdx.x, b = bm >> 5;
    const int n0 = blockIdx.y;
    const int tid = threadIdx.x;
    const int wid = tid >> 5, lane = tid & 31;
    const int wm = (wid >> 2) * 64, wn = (wid & 3) * 32;

    const int row = tid >> 1, seg = tid & 1;
    const uint32_t rowoff = (uint32_t)(row * 128 + seg * 64);

    const __half* vrow = vp16 + (size_t)(b * 128 + row) * 256 + seg * 32;
    const __half* wrow = wp + (size_t)(n0 * 128 + row) * 256 + seg * 32;

    // ---- group 0: all 4 A chunks (raw vp16) + B chunk 0 ----
#pragma unroll
    for (int kc = 0; kc < 4; kc++)
#pragma unroll
        for (int j = 0; j < 4; j++)
            cp16(sb + kc * 16384 + SWZ(rowoff + j * 16), vrow + kc * 64 + j * 8);
#pragma unroll
    for (int j = 0; j < 4; j++)
        cp16(sb + OFF_B + SWZ(rowoff + j * 16), wrow + j * 8);
    cp_commit();
    // ---- group 1: B chunk 1 ----
#pragma unroll
    for (int j = 0; j < 4; j++)
        cp16(sb + OFF_B + BBUF + SWZ(rowoff + j * 16), wrow + 64 + j * 8);
    cp_commit();

    // ---- up16[bm] -> smem (128 half2) ----
    __half2* ups2 = (__half2*)(smp + OFF_UPS);
    if (tid < 128) ups2[tid] = ((const __half2*)(up16 + (size_t)bm * 256))[tid];

    cp_wait<1>();      // group0 done: A + B0
    __syncthreads();   // + ups2 visible

    float c[4][4][4];
#pragma unroll
    for (int i = 0; i < 4; i++)
#pragma unroll
        for (int j = 0; j < 4; j++)
#pragma unroll
            for (int q = 0; q < 4; q++) c[i][j][q] = 0.f;

    const int lq = lane & 3;

#pragma unroll
    for (int kc = 0; kc < 4; kc++) {
        uint32_t abase = sb + (uint32_t)kc * 16384;
        uint32_t bbase = sb + OFF_B + (uint32_t)(kc & 1) * BBUF;
#pragma unroll
        for (int ks = 0; ks < 4; ks++) {
            const int ksg = kc * 4 + ks;
            const __half2 mul0 = ups2[ksg * 8 + lq];
            const __half2 mul1 = ups2[ksg * 8 + 4 + lq];
            uint32_t a[4][4], bfr[4][2];
            const uint32_t acol = (uint32_t)(ks * 32 + (lane >> 4) * 16);
#pragma unroll
            for (int mi = 0; mi < 4; mi++) {
                uint32_t ro = (uint32_t)((wm + mi * 16 + (lane & 15)) * 128) + acol;
                ldsm4(a[mi][0], a[mi][1], a[mi][2], a[mi][3], abase + SWZ(ro));
                a[mi][0] = hmul2u(a[mi][0], mul0);
                a[mi][1] = hmul2u(a[mi][1], mul0);
                a[mi][2] = hmul2u(a[mi][2], mul1);
                a[mi][3] = hmul2u(a[mi][3], mul1);
            }
#pragma unroll
            for (int np = 0; np < 2; np++) {
                uint32_t ro = (uint32_t)((wn + np * 16 + (lane & 15)) * 128) + acol;
                uint32_t m0, m1, m2, m3;
                ldsm4(m0, m1, m2, m3, bbase + SWZ(ro));
                bfr[2 * np][0] = m0; bfr[2 * np][1] = m2;
                bfr[2 * np + 1][0] = m1; bfr[2 * np + 1][1] = m3;
            }
#pragma unroll
            for (int mi = 0; mi < 4; mi++)
#pragma unroll
                for (int nj = 0; nj < 4; nj++)
                    mma_f16(c[mi][nj], a[mi], bfr[nj]);
        }
        // B pipeline: buf (kc&1) just consumed; refill with chunk kc+2
        if (kc < 2) {
            __syncthreads();                       // all warps done with buf kc&1
            uint32_t dstb = sb + OFF_B + (uint32_t)(kc & 1) * BBUF;
#pragma unroll
            for (int j = 0; j < 4; j++)
                cp16(dstb + SWZ(rowoff + j * 16), wrow + (kc + 2) * 64 + j * 8);
            cp_commit();
            cp_wait<1>();                          // B chunk kc+1 ready
            __syncthreads();
        } else if (kc == 2) {
            cp_wait<0>();                          // B chunk 3 ready
            __syncthreads();
        }
    }

    // ---- epilogue: +bias, relu, store ----
    const int rin = lane >> 2, cin = (lane & 3) * 2;
    float* obase = out + (size_t)bm * 128 * 256 + n0 * 128;
#pragma unroll
    for (int nj = 0; nj < 4; nj++) {
        const int f = wn + nj * 8 + cin;
        const float b0 = bp[n0 * 128 + f], b1 = bp[n0 * 128 + f + 1];
#pragma unroll
        for (int mi = 0; mi < 4; mi++) {
            float* p0 = obase + (size_t)(wm + mi * 16 + rin) * 256 + f;
            *(float2*)p0 = make_float2(fmaxf(c[mi][nj][0] + b0, 0.f),
                                       fmaxf(c[mi][nj][1] + b1, 0.f));
            *(float2*)(p0 + 8 * 256) = make_float2(fmaxf(c[mi][nj][2] + b0, 0.f),
                                                   fmaxf(c[mi][nj][3] + b1, 0.f));
        }
    }
}

// -------------------- host launch -------------------------------------------
extern "C" void kernel_launch(void* const* d_in, const int* in_sizes, int n_in,
                              void* d_out, int out_size) {
    const float* u  = (const float*)d_in[0];   // (32,32,1024)
    const float* v  = (const float*)d_in[1];   // (32,128,2048)
    const float* Wu = (const float*)d_in[2];   // (256,1024)
    const float* Wv = (const float*)d_in[3];   // (256,2048)
    const float* Wp = (const float*)d_in[4];   // (256,256)
    const float* bp = (const float*)d_in[5];   // (256,)
    float* out = (float*)d_out;                // (32,32,128,256)

    float* vpp_p;
    __half *up16, *vp16, *u16, *v16, *wu, *wv, *wp;
    cudaGetSymbolAddress((void**)&vpp_p, g_vp_part);
    cudaGetSymbolAddress((void**)&up16, g_up16);
    cudaGetSymbolAddress((void**)&vp16, g_vp16);
    cudaGetSymbolAddress((void**)&u16, g_u16);
    cudaGetSymbolAddress((void**)&v16, g_v16);
    cudaGetSymbolAddress((void**)&wu, g_wu16);
    cudaGetSymbolAddress((void**)&wv, g_wv16);
    cudaGetSymbolAddress((void**)&wp, g_wp16);

    const int PROJ_SMEM = 2 * 32768 + 1024;          // 66560
    const int FUSE_SMEM = 98304 + 512 + 1024;        // 99840
    cudaFuncSetAttribute(proj_mma, cudaFuncAttributeMaxDynamicSharedMemorySize, PROJ_SMEM);
    cudaFuncSetAttribute(fuse_mma, cudaFuncAttributeMaxDynamicSharedMemorySize, FUSE_SMEM);

    const int total = 1024 * 1024 + 4096 * 2048 + 256 * 1024 + 256 * 2048 + 256 * 256;
    prep_cvt<<<(total / 4 + 255) / 256, 256>>>(u, v, Wu, Wv, Wp, u16, v16, wu, wv, wp);
    proj_mma<<<144, 256, PROJ_SMEM>>>(u16, v16, wu, wv, up16, vpp_p);
    add_parts<<<1024, 256>>>(vpp_p, vp16);
    fuse_mma<<<dim3(1024, 2), 256, FUSE_SMEM>>>(up16, vp16, wp, bp, out);
}

// round 13
// speedup vs baseline: 2.1425x; 1.1083x over previous
#include <cuda_runtime.h>
#include <cuda_fp16.h>
#include <cstdint>

// ============================================================================
// LowRankBilinearFusion, HMMA fp16:
//   prep: u,v,Wu,Wv,Wp -> fp16
//   proj: up16 = u@Wu^T (direct fp16 out); vp_part = v@Wv^T k-split x2 (fp32)
//   add:  vp16 = fp16(part0+part1)
//   fuse: out[bm,n0] = relu(vp16[b] @ (up16[bm] ⊙ Wp16[n0])^T + bp)
//     256 thr, 8 warps (2x4), warp tile 64x32, 2 CTAs/SM.
//     A = RAW vp16 resident (4x16KB, progressive cp.async groups).
//     up16 multiply applied to B FRAGMENTS in registers (8 hmul2/k-step).
//     Correct hoist: addr = base + ra + (acol ^ swzbits(ra))  [add!=xor fix]
// ============================================================================

__device__ float  g_vp_part[2 * 4096 * 256];
__device__ __half g_up16[1024 * 256];
__device__ __half g_vp16[4096 * 256];
__device__ __half g_u16[1024 * 1024];
__device__ __half g_v16[4096 * 2048];
__device__ __half g_wu16[256 * 1024];
__device__ __half g_wv16[256 * 2048];
__device__ __half g_wp16[256 * 256];

#define SWZ(o) ((o) ^ (((o) >> 3) & 0x70))

__device__ __forceinline__ uint32_t smem_u32(const void* p) {
    uint32_t a;
    asm("{ .reg .u64 t; cvta.to.shared.u64 t, %1; cvt.u32.u64 %0, t; }" : "=r"(a) : "l"(p));
    return a;
}
__device__ __forceinline__ void ldsm4(uint32_t& r0, uint32_t& r1, uint32_t& r2, uint32_t& r3,
                                      uint32_t addr) {
    asm volatile("ldmatrix.sync.aligned.m8n8.x4.shared.b16 {%0,%1,%2,%3}, [%4];"
                 : "=r"(r0), "=r"(r1), "=r"(r2), "=r"(r3) : "r"(addr));
}
__device__ __forceinline__ void mma_f16(float* c, const uint32_t* a, const uint32_t* b) {
    asm volatile(
        "mma.sync.aligned.m16n8k16.row.col.f32.f16.f16.f32 "
        "{%0,%1,%2,%3}, {%4,%5,%6,%7}, {%8,%9}, {%0,%1,%2,%3};"
        : "+f"(c[0]), "+f"(c[1]), "+f"(c[2]), "+f"(c[3])
        : "r"(a[0]), "r"(a[1]), "r"(a[2]), "r"(a[3]), "r"(b[0]), "r"(b[1]));
}
__device__ __forceinline__ void cp16(uint32_t dst, const void* src) {
    asm volatile("cp.async.cg.shared.global [%0], [%1], 16;" :: "r"(dst), "l"(src));
}
__device__ __forceinline__ void cp_commit() { asm volatile("cp.async.commit_group;" ::: "memory"); }
template <int N>
__device__ __forceinline__ void cp_wait() { asm volatile("cp.async.wait_group %0;" :: "n"(N) : "memory"); }
__device__ __forceinline__ uint32_t hmul2u(uint32_t a, __half2 m) {
    __half2 r = __hmul2(*(__half2*)&a, m);
    return *(uint32_t*)&r;
}

// -------------------- prep: convert all operands to fp16 ---------------------
__global__ void __launch_bounds__(256) prep_cvt(
    const float* __restrict__ u, const float* __restrict__ v,
    const float* __restrict__ Wu, const float* __restrict__ Wv, const float* __restrict__ Wp,
    __half* u16, __half* v16, __half* wu, __half* wv, __half* wp)
{
    const int N1 = 1024 * 1024, N2 = 4096 * 2048;
    const int N3 = 256 * 1024, N4 = 256 * 2048, N5 = 256 * 256;
    int t = blockIdx.x * 256 + threadIdx.x;
    size_t i = (size_t)t * 4;
    const float* src; __half* dst; size_t j;
    if (i < N1)                          { src = u;  dst = u16; j = i; }
    else if (i < (size_t)N1 + N2)        { src = v;  dst = v16; j = i - N1; }
    else if (i < (size_t)N1 + N2 + N3)   { src = Wu; dst = wu;  j = i - N1 - N2; }
    else if (i < (size_t)N1 + N2 + N3 + N4) { src = Wv; dst = wv; j = i - N1 - N2 - N3; }
    else if (i < (size_t)N1 + N2 + N3 + N4 + N5) { src = Wp; dst = wp; j = i - N1 - N2 - N3 - N4; }
    else return;
    float4 x = *(const float4*)(src + j);
    __half2 h0 = __floats2half2_rn(x.x, x.y);
    __half2 h1 = __floats2half2_rn(x.z, x.w);
    uint2 o; o.x = *(uint32_t*)&h0; o.y = *(uint32_t*)&h1;
    *(uint2*)(dst + j) = o;
}

// ============================================================================
// proj: C[128x128] = A16 @ B16^T, K = 1024 per CTA (16 chunks of 64).
// Grid: 0..15 up (mt8 x n2) -> up16 direct; 16..143 vp (mt32 x n2 x kh2).
// 256 thr, 8 warps 2x4, warp tile 64x32. 2 CTAs/SM.  (unchanged from R11)
// ============================================================================
__global__ void __launch_bounds__(256, 2) proj_mma(
    const __half* __restrict__ u16, const __half* __restrict__ v16,
    const __half* __restrict__ wu, const __half* __restrict__ wv,
    __half* __restrict__ up16, float* __restrict__ vp_part)
{
    extern __shared__ char dsm[];
    uint32_t sb_raw = smem_u32(dsm);
    uint32_t sb = (sb_raw + 1023u) & ~1023u;

    constexpr uint32_t BUF = 32768, OFF_B = 16384;

    const int bid = blockIdx.x;
    const int tid = threadIdx.x;
    const int wid = tid >> 5, lane = tid & 31;
    const int wm = (wid >> 2) * 64, wn = (wid & 3) * 32;

    const __half *A, *B;
    int lda, ldb;
    bool is_up;
    __half* Ch = nullptr; float* Cf = nullptr;
    if (bid < 16) {
        int mt = bid >> 1, n0 = bid & 1;
        A = u16 + (size_t)mt * 128 * 1024; lda = 1024;
        B = wu + (size_t)n0 * 128 * 1024; ldb = 1024;
        Ch = up16 + (size_t)mt * 128 * 256 + n0 * 128;
        is_up = true;
    } else {
        int b2 = bid - 16;
        int mt = b2 >> 2, n0 = (b2 >> 1) & 1, kh = b2 & 1;
        A = v16 + (size_t)mt * 128 * 2048 + kh * 1024; lda = 2048;
        B = wv + (size_t)n0 * 128 * 2048 + kh * 1024; ldb = 2048;
        Cf = vp_part + (size_t)kh * 4096 * 256 + (size_t)mt * 128 * 256 + n0 * 128;
        is_up = false;
    }

    const int row = tid >> 1, seg = tid & 1;
    const __half* pA = A + (size_t)row * lda + seg * 32;
    const __half* pB = B + (size_t)row * ldb + seg * 32;
    const uint32_t rowoff = (uint32_t)(row * 128 + seg * 64);

    float c[4][4][4];
#pragma unroll
    for (int i = 0; i < 4; i++)
#pragma unroll
        for (int j = 0; j < 4; j++)
#pragma unroll
            for (int q = 0; q < 4; q++) c[i][j][q] = 0.f;

    auto issue = [&](int kc, int bf) {
        uint32_t base = sb + (uint32_t)bf * BUF;
#pragma unroll
        for (int j = 0; j < 4; j++) {
            uint32_t sw = SWZ(rowoff + j * 16);
            cp16(base + sw,         pA + kc * 64 + j * 8);
            cp16(base + OFF_B + sw, pB + kc * 64 + j * 8);
        }
    };
    auto mmas = [&](int bf) {
        uint32_t base = sb + (uint32_t)bf * BUF;
#pragma unroll
        for (int ks = 0; ks < 4; ks++) {
            uint32_t a[4][4], bfr[4][2];
            const uint32_t acol = (uint32_t)(ks * 32 + (lane >> 4) * 16);
#pragma unroll
            for (int mi = 0; mi < 4; mi++) {
                uint32_t ro = (uint32_t)((wm + mi * 16 + (lane & 15)) * 128) + acol;
                ldsm4(a[mi][0], a[mi][1], a[mi][2], a[mi][3], base + SWZ(ro));
            }
#pragma unroll
            for (int np = 0; np < 2; np++) {
                uint32_t ro = (uint32_t)((wn + np * 16 + (lane & 15)) * 128) + acol;
                uint32_t m0, m1, m2, m3;
                ldsm4(m0, m1, m2, m3, base + OFF_B + SWZ(ro));
                bfr[2 * np][0] = m0; bfr[2 * np][1] = m2;
                bfr[2 * np + 1][0] = m1; bfr[2 * np + 1][1] = m3;
            }
#pragma unroll
            for (int mi = 0; mi < 4; mi++)
#pragma unroll
                for (int nj = 0; nj < 4; nj++)
                    mma_f16(c[mi][nj], a[mi], bfr[nj]);
        }
    };

    issue(0, 0); cp_commit();
    for (int kc = 0; kc < 16; kc++) {
        if (kc < 15) { issue(kc + 1, (kc + 1) & 1); cp_commit(); cp_wait<1>(); }
        else cp_wait<0>();
        __syncthreads();
        mmas(kc & 1);
        __syncthreads();
    }

    const int rin = lane >> 2, cin = (lane & 3) * 2;
    if (is_up) {
#pragma unroll
        for (int mi = 0; mi < 4; mi++)
#pragma unroll
            for (int nj = 0; nj < 4; nj++) {
                __half* p0 = Ch + (size_t)(wm + mi * 16 + rin) * 256 + wn + nj * 8 + cin;
                __half2 h0 = __floats2half2_rn(c[mi][nj][0], c[mi][nj][1]);
                __half2 h1 = __floats2half2_rn(c[mi][nj][2], c[mi][nj][3]);
                *(__half2*)p0 = h0;
                *(__half2*)(p0 + 8 * 256) = h1;
            }
    } else {
#pragma unroll
        for (int mi = 0; mi < 4; mi++)
#pragma unroll
            for (int nj = 0; nj < 4; nj++) {
                float* p0 = Cf + (size_t)(wm + mi * 16 + rin) * 256 + wn + nj * 8 + cin;
                *(float2*)p0 = make_float2(c[mi][nj][0], c[mi][nj][1]);
                *(float2*)(p0 + 8 * 256) = make_float2(c[mi][nj][2], c[mi][nj][3]);
            }
    }
}

// -------------------- add: vp16 = fp16(part0 + part1) ------------------------
__global__ void __launch_bounds__(256) add_parts(
    const float* __restrict__ vpp, __half* __restrict__ vp16)
{
    size_t i = ((size_t)blockIdx.x * 256 + threadIdx.x) * 4;
    float4 a = *(const float4*)(vpp + i);
    float4 b = *(const float4*)(vpp + (size_t)4096 * 256 + i);
    __half2 h0 = __floats2half2_rn(a.x + b.x, a.y + b.y);
    __half2 h1 = __floats2half2_rn(a.z + b.z, a.w + b.w);
    uint2 o; o.x = *(uint32_t*)&h0; o.y = *(uint32_t*)&h1;
    *(uint2*)(vp16 + i) = o;
}

// ============================================================================
// fuse: out[bm, n0] = relu(vp16[b] @ (up16[bm] ⊙ Wp16[n0])^T + bp)
// 128 x 128 per CTA, K=256. 256 threads, 8 warps (2x4), warp tile 64x32.
// A = raw vp16 resident, progressive groups (A0,B0),(A1,B1),(A2),(A3).
// up16 applied to B fragments. Hoist fix: addr = base + ra + (acol ^ sz).
// 2 CTAs/SM.
// ============================================================================
__global__ void __launch_bounds__(256, 2) fuse_mma(
    const __half* __restrict__ up16, const __half* __restrict__ vp16,
    const __half* __restrict__ wp, const float* __restrict__ bp,
    float* __restrict__ out)
{
    extern __shared__ char dsm[];
    uint32_t sb_raw = smem_u32(dsm);
    uint32_t sb = (sb_raw + 1023u) & ~1023u;
    char* smp = dsm + (sb - sb_raw);

    constexpr uint32_t OFF_B = 65536, BBUF = 16384, OFF_UPS = 98304;

    const int bm = blockIdx.x, b = bm >> 5;
    const int n0 = blockIdx.y;
    const int tid = threadIdx.x;
    const int wid = tid >> 5, lane = tid & 31;
    const int wm = (wid >> 2) * 64, wn = (wid & 3) * 32;

    const int row = tid >> 1, seg = tid & 1;
    const uint32_t rowoff = (uint32_t)(row * 128 + seg * 64);

    const __half* vrow = vp16 + (size_t)(b * 128 + row) * 256 + seg * 32;
    const __half* wrow = wp + (size_t)(n0 * 128 + row) * 256 + seg * 32;

    // ---- progressive prologue: g0=(A0,B0), g1=(A1,B1), g2=(A2), g3=(A3) ----
#pragma unroll
    for (int j = 0; j < 4; j++) {
        uint32_t sw = SWZ(rowoff + j * 16);
        cp16(sb + sw, vrow + j * 8);
        cp16(sb + OFF_B + sw, wrow + j * 8);
    }
    cp_commit();
#pragma unroll
    for (int j = 0; j < 4; j++) {
        uint32_t sw = SWZ(rowoff + j * 16);
        cp16(sb + 16384 + sw, vrow + 64 + j * 8);
        cp16(sb + OFF_B + BBUF + sw, wrow + 64 + j * 8);
    }
    cp_commit();
#pragma unroll
    for (int j = 0; j < 4; j++)
        cp16(sb + 32768 + SWZ(rowoff + j * 16), vrow + 128 + j * 8);
    cp_commit();
#pragma unroll
    for (int j = 0; j < 4; j++)
        cp16(sb + 49152 + SWZ(rowoff + j * 16), vrow + 192 + j * 8);
    cp_commit();

    // ---- up16[bm] -> smem (128 half2) ----
    __half2* ups2 = (__half2*)(smp + OFF_UPS);
    if (tid < 128) ups2[tid] = ((const __half2*)(up16 + (size_t)bm * 256))[tid];

    cp_wait<3>();      // g0 done: A0 + B0
    __syncthreads();   // + ups2 visible

    // ---- hoisted row bases and their swizzle bits (kept SEPARATE) ----
    uint32_t ra[4], sa[4], rb[2], sbz[2];
#pragma unroll
    for (int mi = 0; mi < 4; mi++) {
        ra[mi] = (uint32_t)((wm + mi * 16 + (lane & 15)) * 128);
        sa[mi] = (ra[mi] >> 3) & 0x70;
    }
#pragma unroll
    for (int np = 0; np < 2; np++) {
        rb[np] = (uint32_t)((wn + np * 16 + (lane & 15)) * 128);
        sbz[np] = (rb[np] >> 3) & 0x70;
    }
    const uint32_t acl = (uint32_t)((lane >> 4) * 16);
    const int lq = lane & 3;

    float c[4][4][4];
#pragma unroll
    for (int i = 0; i < 4; i++)
#pragma unroll
        for (int j = 0; j < 4; j++)
#pragma unroll
            for (int q = 0; q < 4; q++) c[i][j][q] = 0.f;

#pragma unroll
    for (int kc = 0; kc < 4; kc++) {
        uint32_t abase = sb + (uint32_t)kc * 16384;
        uint32_t bbase = sb + OFF_B + (uint32_t)(kc & 1) * BBUF;
#pragma unroll
        for (int ks = 0; ks < 4; ks++) {
            const int ksg = kc * 4 + ks;
            const __half2 mul0 = ups2[ksg * 8 + lq];
            const __half2 mul1 = ups2[ksg * 8 + 4 + lq];
            const uint32_t acol = (uint32_t)(ks * 32) + acl;
            uint32_t a[4][4], bfr[4][2];
#pragma unroll
            for (int mi = 0; mi < 4; mi++)
                ldsm4(a[mi][0], a[mi][1], a[mi][2], a[mi][3],
                      abase + ra[mi] + (acol ^ sa[mi]));
#pragma unroll
            for (int np = 0; np < 2; np++) {
                uint32_t m0, m1, m2, m3;
                ldsm4(m0, m1, m2, m3, bbase + rb[np] + (acol ^ sbz[np]));
                bfr[2 * np][0]     = hmul2u(m0, mul0);
                bfr[2 * np][1]     = hmul2u(m2, mul1);
                bfr[2 * np + 1][0] = hmul2u(m1, mul0);
                bfr[2 * np + 1][1] = hmul2u(m3, mul1);
            }
#pragma unroll
            for (int mi = 0; mi < 4; mi++)
#pragma unroll
                for (int nj = 0; nj < 4; nj++)
                    mma_f16(c[mi][nj], a[mi], bfr[nj]);
        }
        // pipeline control
        if (kc == 0) {
            __syncthreads();                       // all warps done with B buf0
#pragma unroll
            for (int j = 0; j < 4; j++)            // B2 -> buf0 (g4)
                cp16(sb + OFF_B + SWZ(rowoff + j * 16), wrow + 128 + j * 8);
            cp_commit();
            cp_wait<3>();                          // g1 done (A1 + B1)
            __syncthreads();
        } else if (kc == 1) {
            __syncthreads();                       // done with B buf1
#pragma unroll
            for (int j = 0; j < 4; j++)            // B3 -> buf1 (g5)
                cp16(sb + OFF_B + BBUF + SWZ(rowoff + j * 16), wrow + 192 + j * 8);
            cp_commit();
            cp_wait<1>();                          // g2,g3,g4 done (A2,A3,B2)
            __syncthreads();
        } else if (kc == 2) {
            cp_wait<0>();                          // g5 done (B3)
            __syncthreads();
        }
    }

    // ---- epilogue: +bias, relu, store ----
    const int rin = lane >> 2, cin = (lane & 3) * 2;
    float* obase = out + (size_t)bm * 128 * 256 + n0 * 128;
#pragma unroll
    for (int nj = 0; nj < 4; nj++) {
        const int f = wn + nj * 8 + cin;
        const float b0 = bp[n0 * 128 + f], b1 = bp[n0 * 128 + f + 1];
#pragma unroll
        for (int mi = 0; mi < 4; mi++) {
            float* p0 = obase + (size_t)(wm + mi * 16 + rin) * 256 + f;
            *(float2*)p0 = make_float2(fmaxf(c[mi][nj][0] + b0, 0.f),
                                       fmaxf(c[mi][nj][1] + b1, 0.f));
            *(float2*)(p0 + 8 * 256) = make_float2(fmaxf(c[mi][nj][2] + b0, 0.f),
                                                   fmaxf(c[mi][nj][3] + b1, 0.f));
        }
    }
}

// -------------------- host launch -------------------------------------------
extern "C" void kernel_launch(void* const* d_in, const int* in_sizes, int n_in,
                              void* d_out, int out_size) {
    const float* u  = (const float*)d_in[0];   // (32,32,1024)
    const float* v  = (const float*)d_in[1];   // (32,128,2048)
    const float* Wu = (const float*)d_in[2];   // (256,1024)
    const float* Wv = (const float*)d_in[3];   // (256,2048)
    const float* Wp = (const float*)d_in[4];   // (256,256)
    const float* bp = (const float*)d_in[5];   // (256,)
    float* out = (float*)d_out;                // (32,32,128,256)

    float* vpp_p;
    __half *up16, *vp16, *u16, *v16, *wu, *wv, *wp;
    cudaGetSymbolAddress((void**)&vpp_p, g_vp_part);
    cudaGetSymbolAddress((void**)&up16, g_up16);
    cudaGetSymbolAddress((void**)&vp16, g_vp16);
    cudaGetSymbolAddress((void**)&u16, g_u16);
    cudaGetSymbolAddress((void**)&v16, g_v16);
    cudaGetSymbolAddress((void**)&wu, g_wu16);
    cudaGetSymbolAddress((void**)&wv, g_wv16);
    cudaGetSymbolAddress((void**)&wp, g_wp16);

    const int PROJ_SMEM = 2 * 32768 + 1024;          // 66560
    const int FUSE_SMEM = 98304 + 512 + 1024;        // 99840
    cudaFuncSetAttribute(proj_mma, cudaFuncAttributeMaxDynamicSharedMemorySize, PROJ_SMEM);
    cudaFuncSetAttribute(fuse_mma, cudaFuncAttributeMaxDynamicSharedMemorySize, FUSE_SMEM);

    const int total = 1024 * 1024 + 4096 * 2048 + 256 * 1024 + 256 * 2048 + 256 * 256;
    prep_cvt<<<(total / 4 + 255) / 256, 256>>>(u, v, Wu, Wv, Wp, u16, v16, wu, wv, wp);
    proj_mma<<<144, 256, PROJ_SMEM>>>(u16, v16, wu, wv, up16, vpp_p);
    add_parts<<<1024, 256>>>(vpp_p, vp16);
    fuse_mma<<<dim3(1024, 2), 256, FUSE_SMEM>>>(up16, vp16, wp, bp, out);
}